// round 1
// baseline (speedup 1.0000x reference)
#include <cuda_runtime.h>
#include <stdint.h>

// Problem constants (fixed-shape problem): N=100000, W=32, D=32.
// Output row = W*D + W + W = 1088 floats = 272 float4.
// Layout per row i: [ gathered x (1024 f) | dis (32 f) | angle (32 f) ]

static const int ROW_F4 = 272;   // float4 per output row
static const int GATHER_F4 = 256; // first 256 float4 are the gather region

__device__ int g_idx_is_i64;

// Detect whether idx is stored as int64 or int32.
// Values are uniform in [0, 100000). If int64 (little-endian), every odd
// 32-bit word is 0. If int32, 32 random odd-position values being all zero
// has probability ~1e-160. Deterministic given the input.
__global__ void detect_idx_dtype_kernel(const int* __restrict__ idx32) {
    int ored = 0;
#pragma unroll
    for (int k = 0; k < 32; k++) {
        ored |= idx32[2 * k + 1];
    }
    g_idx_is_i64 = (ored == 0) ? 1 : 0;
}

__global__ __launch_bounds__(256)
void fused_gather_concat_kernel(const float4* __restrict__ x4,
                                const void*  __restrict__ idx,
                                const float4* __restrict__ dis4,
                                const float4* __restrict__ ang4,
                                float4* __restrict__ out4,
                                int total_f4)  // N * 272
{
    int t = blockIdx.x * blockDim.x + threadIdx.x;
    if (t >= total_f4) return;

    int i = t / ROW_F4;          // output row
    int r = t - i * ROW_F4;      // float4 within row

    if (r < GATHER_F4) {
        int w   = r >> 3;        // which neighbor (0..31)
        int seg = r & 7;         // which float4 of the 32-float x row
        long long j;
        if (g_idx_is_i64) {
            j = ((const long long*)idx)[(long long)i * 32 + w];
        } else {
            j = (long long)((const int*)idx)[i * 32 + w];
        }
        out4[t] = x4[j * 8 + seg];
    } else if (r < GATHER_F4 + 8) {
        out4[t] = dis4[i * 8 + (r - GATHER_F4)];
    } else {
        out4[t] = ang4[i * 8 + (r - GATHER_F4 - 8)];
    }
}

extern "C" void kernel_launch(void* const* d_in, const int* in_sizes, int n_in,
                              void* d_out, int out_size)
{
    // Inputs in reference order: x [N,32] f32, idx [N,32] (i64 or i32),
    // dis [N,32] f32, angle [N,32] f32.
    const float4* x4   = (const float4*)d_in[0];
    const void*   idx  = d_in[1];
    const float4* dis4 = (const float4*)d_in[2];
    const float4* ang4 = (const float4*)d_in[3];
    float4* out4 = (float4*)d_out;

    const int n_rows = in_sizes[0] / 32;        // N (x has N*32 elements)
    const int total_f4 = n_rows * ROW_F4;       // = out_size / 4

    detect_idx_dtype_kernel<<<1, 1>>>((const int*)idx);

    int threads = 256;
    int blocks = (total_f4 + threads - 1) / threads;
    fused_gather_concat_kernel<<<blocks, threads>>>(x4, idx, dis4, ang4, out4,
                                                    total_f4);
}

// round 2
// speedup vs baseline: 1.4176x; 1.4176x over previous
#include <cuda_runtime.h>
#include <stdint.h>

// N=100000, W=32, D=32. Output row = 1088 floats = 272 float4.
// Per row i: [ gathered x (256 f4) | dis (8 f4) | angle (8 f4) ]

#define ROW_F4    272
#define GATHER_F4 256
#define UNROLL    4

__device__ int g_idx_is_i64;

// idx values are < 100000. If stored as little-endian int64, all odd 32-bit
// words are zero. If int32, 32 random odd words all-zero has p ~ 1e-160.
__global__ void detect_idx_dtype_kernel(const int* __restrict__ idx32) {
    int ored = 0;
#pragma unroll
    for (int k = 0; k < 32; k++) ored |= idx32[2 * k + 1];
    g_idx_is_i64 = (ored == 0) ? 1 : 0;
}

__global__ __launch_bounds__(256)
void fused_gather_concat_kernel(const float4* __restrict__ x4,
                                const void*  __restrict__ idx,
                                const float4* __restrict__ dis4,
                                const float4* __restrict__ ang4,
                                float4* __restrict__ out4,
                                int total_f4)
{
    const int stride = gridDim.x * blockDim.x;
    const int t0 = blockIdx.x * blockDim.x + threadIdx.x;
    const int is64 = g_idx_is_i64;   // uniform

    const float4* __restrict__ src[UNROLL];
    bool valid[UNROLL];
    float4 v[UNROLL];

    // Phase 1: compute all source addresses (independent short chains:
    // the gather slots each need one idx load, but the 4 slots overlap).
#pragma unroll
    for (int k = 0; k < UNROLL; k++) {
        int tk = t0 + k * stride;
        valid[k] = (tk < total_f4);
        if (valid[k]) {
            int i = tk / ROW_F4;
            int r = tk - i * ROW_F4;
            if (r < GATHER_F4) {
                int w   = r >> 3;
                int seg = r & 7;
                long long j;
                if (is64) j = ((const long long*)idx)[(long long)i * 32 + w];
                else      j = (long long)((const int*)idx)[i * 32 + w];
                src[k] = x4 + j * 8 + seg;
            } else if (r < GATHER_F4 + 8) {
                src[k] = dis4 + i * 8 + (r - GATHER_F4);
            } else {
                src[k] = ang4 + i * 8 + (r - GATHER_F4 - 8);
            }
        }
    }

    // Phase 2: issue the 4 independent gathers.
#pragma unroll
    for (int k = 0; k < UNROLL; k++) {
        if (valid[k]) v[k] = __ldg(src[k]);
    }

    // Phase 3: coalesced stores (each k-slice is a contiguous warp write).
#pragma unroll
    for (int k = 0; k < UNROLL; k++) {
        if (valid[k]) out4[t0 + k * stride] = v[k];
    }
}

extern "C" void kernel_launch(void* const* d_in, const int* in_sizes, int n_in,
                              void* d_out, int out_size)
{
    const float4* x4   = (const float4*)d_in[0];
    const void*   idx  = d_in[1];
    const float4* dis4 = (const float4*)d_in[2];
    const float4* ang4 = (const float4*)d_in[3];
    float4* out4 = (float4*)d_out;

    const int n_rows   = in_sizes[0] / 32;   // N
    const int total_f4 = n_rows * ROW_F4;

    detect_idx_dtype_kernel<<<1, 1>>>((const int*)idx);

    const int threads = 256;
    const int per_blk = threads * UNROLL;
    const int blocks  = (total_f4 + per_blk - 1) / per_blk;
    fused_gather_concat_kernel<<<blocks, threads>>>(x4, idx, dis4, ang4, out4,
                                                    total_f4);
}

// round 3
// speedup vs baseline: 1.8418x; 1.2993x over previous
#include <cuda_runtime.h>
#include <stdint.h>

// N=100000, W=32, D=32. Output row = 1088 floats = 272 float4.
// Per row i: [ gathered x rows (256 f4) | dis (8 f4) | angle (8 f4) ]
// Warp-per-row: lane l loads idx[i*32+l]; 8 gather iterations use shfl to
// get the neighbor index; stores are fully coalesced 32-lane float4 writes.

#define ROW_F4 272

__device__ int g_idx_is_i64;

// idx values < 100000. If little-endian int64, all odd 32-bit words are 0.
// If int32, 32 random odd words all-zero has p ~ 1e-160.
__global__ void detect_idx_dtype_kernel(const int* __restrict__ idx32) {
    int ored = 0;
#pragma unroll
    for (int k = 0; k < 32; k++) ored |= idx32[2 * k + 1];
    g_idx_is_i64 = (ored == 0) ? 1 : 0;
}

__global__ __launch_bounds__(256)
void fused_gather_concat_warp_kernel(const float4* __restrict__ x4,
                                     const void*  __restrict__ idx,
                                     const float4* __restrict__ dis4,
                                     const float4* __restrict__ ang4,
                                     float4* __restrict__ out4,
                                     int n_rows)
{
    const int warp_id = (blockIdx.x * blockDim.x + threadIdx.x) >> 5;
    const int lane    = threadIdx.x & 31;
    if (warp_id >= n_rows) return;
    const int i = warp_id;

    // One idx load per lane (coalesced). Indices fit in int32.
    int ji;
    if (g_idx_is_i64) {
        ji = (int)((const long long*)idx)[(long long)i * 32 + lane];
    } else {
        ji = ((const int*)idx)[i * 32 + lane];
    }

    // Phase 1: distribute all 8 needed neighbor indices via shuffle (4cyc each).
    const int wbase = lane >> 3;          // which lane-group (0..3)
    const int seg   = lane & 7;           // float4 within the 32-float x row
    int jw[8];
#pragma unroll
    for (int it = 0; it < 8; it++)
        jw[it] = __shfl_sync(0xffffffffu, ji, it * 4 + wbase);

    // Phase 2: 8 independent gather loads (MLP=8).
    float4 v[8];
#pragma unroll
    for (int it = 0; it < 8; it++)
        v[it] = __ldg(x4 + (long long)jw[it] * 8 + seg);

    // Phase 3: 8 fully coalesced stores.
    float4* __restrict__ orow = out4 + (long long)i * ROW_F4;
#pragma unroll
    for (int it = 0; it < 8; it++)
        orow[it * 32 + lane] = v[it];

    // Tail: dis (8 f4) then angle (8 f4), lanes 0..15 (one coalesced 256B write).
    if (lane < 8)
        orow[256 + lane] = __ldg(dis4 + i * 8 + lane);
    else if (lane < 16)
        orow[256 + lane] = __ldg(ang4 + i * 8 + (lane - 8));
}

extern "C" void kernel_launch(void* const* d_in, const int* in_sizes, int n_in,
                              void* d_out, int out_size)
{
    const float4* x4   = (const float4*)d_in[0];
    const void*   idx  = d_in[1];
    const float4* dis4 = (const float4*)d_in[2];
    const float4* ang4 = (const float4*)d_in[3];
    float4* out4 = (float4*)d_out;

    const int n_rows = in_sizes[0] / 32;   // N

    detect_idx_dtype_kernel<<<1, 1>>>((const int*)idx);

    const int threads = 256;                       // 8 warps/block
    const int blocks  = (n_rows + 7) / 8;          // one warp per row
    fused_gather_concat_warp_kernel<<<blocks, threads>>>(x4, idx, dis4, ang4,
                                                         out4, n_rows);
}

// round 4
// speedup vs baseline: 1.8971x; 1.0300x over previous
#include <cuda_runtime.h>
#include <stdint.h>

// N=100000, W=32, D=32. Output row = 1088 floats = 272 float4.
// Per row i: [ gathered x rows (256 f4) | dis (8 f4) | angle (8 f4) ]
// Warp-per-row; streaming (evict-first) stores protect x's L2 residency.

#define ROW_F4 272

__device__ int g_idx_is_i64;

// idx values < 100000. If little-endian int64, all odd 32-bit words are 0.
// If int32, 32 random odd words all-zero has p ~ 1e-160.
__global__ void detect_idx_dtype_kernel(const int* __restrict__ idx32) {
    int ored = 0;
#pragma unroll
    for (int k = 0; k < 32; k++) ored |= idx32[2 * k + 1];
    g_idx_is_i64 = (ored == 0) ? 1 : 0;
}

__global__ __launch_bounds__(256)
void fused_gather_concat_warp_kernel(const float4* __restrict__ x4,
                                     const void*  __restrict__ idx,
                                     const float4* __restrict__ dis4,
                                     const float4* __restrict__ ang4,
                                     float4* __restrict__ out4,
                                     int n_rows)
{
    const int warp_id = (blockIdx.x * blockDim.x + threadIdx.x) >> 5;
    const int lane    = threadIdx.x & 31;
    if (warp_id >= n_rows) return;
    const int i = warp_id;

    // One idx load per lane (coalesced, read-once -> streaming).
    int ji;
    if (g_idx_is_i64) {
        ji = (int)__ldcs((const long long*)idx + (long long)i * 32 + lane);
    } else {
        ji = __ldcs((const int*)idx + i * 32 + lane);
    }

    // Distribute the 8 needed neighbor indices via shuffle (4cyc each).
    const int wbase = lane >> 3;          // lane-group (0..3)
    const int seg   = lane & 7;           // float4 within the 32-float x row
    int jw[8];
#pragma unroll
    for (int it = 0; it < 8; it++)
        jw[it] = __shfl_sync(0xffffffffu, ji, it * 4 + wbase);

    // 8 independent gather loads (MLP=8). x is hot in L2 -> keep default .ca.
    float4 v[8];
#pragma unroll
    for (int it = 0; it < 8; it++)
        v[it] = __ldg(x4 + (long long)jw[it] * 8 + seg);

    // 8 fully coalesced streaming stores (evict-first: output never re-read,
    // protects x's L2 residency from write-allocate pollution).
    float4* __restrict__ orow = out4 + (long long)i * ROW_F4;
#pragma unroll
    for (int it = 0; it < 8; it++)
        __stcs(orow + it * 32 + lane, v[it]);

    // Tail: dis (8 f4) then angle (8 f4), lanes 0..15 (read-once -> streaming).
    if (lane < 8)
        __stcs(orow + 256 + lane, __ldcs(dis4 + i * 8 + lane));
    else if (lane < 16)
        __stcs(orow + 256 + lane, __ldcs(ang4 + i * 8 + (lane - 8)));
}

extern "C" void kernel_launch(void* const* d_in, const int* in_sizes, int n_in,
                              void* d_out, int out_size)
{
    const float4* x4   = (const float4*)d_in[0];
    const void*   idx  = d_in[1];
    const float4* dis4 = (const float4*)d_in[2];
    const float4* ang4 = (const float4*)d_in[3];
    float4* out4 = (float4*)d_out;

    const int n_rows = in_sizes[0] / 32;   // N

    detect_idx_dtype_kernel<<<1, 1>>>((const int*)idx);

    const int threads = 256;                       // 8 warps/block
    const int blocks  = (n_rows + 7) / 8;          // one warp per row
    fused_gather_concat_warp_kernel<<<blocks, threads>>>(x4, idx, dis4, ang4,
                                                         out4, n_rows);
}

// round 5
// speedup vs baseline: 1.9359x; 1.0204x over previous
#include <cuda_runtime.h>
#include <stdint.h>

// N=100000, W=32, D=32. Output row = 1088 floats = 272 float4.
// Per row i: [ gathered x rows (256 f4) | dis (8 f4) | angle (8 f4) ]
// Warp handles TWO rows: MLP=16 gathers, fully packed tail store.

#define ROW_F4 272

__device__ int g_idx_is_i64;

// idx values < 100000. If little-endian int64, all odd 32-bit words are 0.
// If int32, 32 random odd words all-zero has p ~ 1e-160.
__global__ void detect_idx_dtype_kernel(const int* __restrict__ idx32) {
    int ored = 0;
#pragma unroll
    for (int k = 0; k < 32; k++) ored |= idx32[2 * k + 1];
    g_idx_is_i64 = (ored == 0) ? 1 : 0;
}

__global__ __launch_bounds__(256)
void fused_gather_concat_warp2_kernel(const float4* __restrict__ x4,
                                      const void*  __restrict__ idx,
                                      const float4* __restrict__ dis4,
                                      const float4* __restrict__ ang4,
                                      float4* __restrict__ out4,
                                      int n_rows)
{
    const int warp_id = (blockIdx.x * blockDim.x + threadIdx.x) >> 5;
    const int lane    = threadIdx.x & 31;
    const int i0 = warp_id * 2;
    const int i1 = i0 + 1;
    if (i0 >= n_rows) return;
    const bool has1 = (i1 < n_rows);

    // One idx load per lane per row (coalesced, read-once).
    int ja, jb = 0;
    if (g_idx_is_i64) {
        ja = (int)__ldcs((const long long*)idx + (long long)i0 * 32 + lane);
        if (has1) jb = (int)__ldcs((const long long*)idx + (long long)i1 * 32 + lane);
    } else {
        ja = __ldcs((const int*)idx + i0 * 32 + lane);
        if (has1) jb = __ldcs((const int*)idx + i1 * 32 + lane);
    }

    const int wbase = lane >> 3;   // lane-group (0..3)
    const int seg   = lane & 7;    // float4 within the 32-float x row

    // Distribute needed neighbor indices via shuffle.
    int jwa[8], jwb[8];
#pragma unroll
    for (int it = 0; it < 8; it++) {
        jwa[it] = __shfl_sync(0xffffffffu, ja, it * 4 + wbase);
        jwb[it] = __shfl_sync(0xffffffffu, jb, it * 4 + wbase);
    }

    // 16 independent gathers (MLP=16). Skip L1 allocate: x working set
    // (12.8MB) can't live in L1; .cg avoids fill-wavefront overhead.
    float4 va[8], vb[8];
#pragma unroll
    for (int it = 0; it < 8; it++)
        va[it] = __ldcg(x4 + (long long)jwa[it] * 8 + seg);
    if (has1) {
#pragma unroll
        for (int it = 0; it < 8; it++)
            vb[it] = __ldcg(x4 + (long long)jwb[it] * 8 + seg);
    }

    // Coalesced streaming stores.
    float4* __restrict__ orow0 = out4 + (long long)i0 * ROW_F4;
#pragma unroll
    for (int it = 0; it < 8; it++)
        __stcs(orow0 + it * 32 + lane, va[it]);
    if (has1) {
        float4* __restrict__ orow1 = out4 + (long long)i1 * ROW_F4;
#pragma unroll
        for (int it = 0; it < 8; it++)
            __stcs(orow1 + it * 32 + lane, vb[it]);

        // Packed tail: lanes 0-15 -> row0 [dis|angle], lanes 16-31 -> row1.
        float4 tv;
        if (lane < 8)        tv = __ldcs(dis4 + i0 * 8 + lane);
        else if (lane < 16)  tv = __ldcs(ang4 + i0 * 8 + (lane - 8));
        else if (lane < 24)  tv = __ldcs(dis4 + i1 * 8 + (lane - 16));
        else                 tv = __ldcs(ang4 + i1 * 8 + (lane - 24));

        if (lane < 16) __stcs(orow0 + 256 + lane, tv);
        else           __stcs(orow1 + 256 + (lane - 16), tv);
    } else {
        if (lane < 8)
            __stcs(orow0 + 256 + lane, __ldcs(dis4 + i0 * 8 + lane));
        else if (lane < 16)
            __stcs(orow0 + 256 + lane, __ldcs(ang4 + i0 * 8 + (lane - 8)));
    }
}

extern "C" void kernel_launch(void* const* d_in, const int* in_sizes, int n_in,
                              void* d_out, int out_size)
{
    const float4* x4   = (const float4*)d_in[0];
    const void*   idx  = d_in[1];
    const float4* dis4 = (const float4*)d_in[2];
    const float4* ang4 = (const float4*)d_in[3];
    float4* out4 = (float4*)d_out;

    const int n_rows = in_sizes[0] / 32;   // N

    detect_idx_dtype_kernel<<<1, 1>>>((const int*)idx);

    const int threads = 256;                        // 8 warps/block
    const int rows_per_block = 16;                  // 2 rows per warp
    const int blocks = (n_rows + rows_per_block - 1) / rows_per_block;
    fused_gather_concat_warp2_kernel<<<blocks, threads>>>(x4, idx, dis4, ang4,
                                                          out4, n_rows);
}

// round 6
// speedup vs baseline: 1.9470x; 1.0058x over previous
#include <cuda_runtime.h>
#include <stdint.h>

// N=100000, W=32, D=32. Output row = 1088 floats = 272 float4.
// Per row i: [ gathered x rows (256 f4) | dis (8 f4) | angle (8 f4) ]
// Warp handles TWO rows. Single-kernel: idx dtype (i64 vs i32) detected
// in-warp from the first 32 odd 32-bit words of idx (broadcast read).

#define ROW_F4 272

__global__ __launch_bounds__(256)
void fused_gather_concat_warp2_kernel(const float4* __restrict__ x4,
                                      const void*  __restrict__ idx,
                                      const float4* __restrict__ dis4,
                                      const float4* __restrict__ ang4,
                                      float4* __restrict__ out4,
                                      int n_rows)
{
    const int warp_id = (blockIdx.x * blockDim.x + threadIdx.x) >> 5;
    const int lane    = threadIdx.x & 31;

    // Dtype detection, warp-local (values < 100000: if little-endian int64,
    // all odd 32-bit words are 0; 32 random i32 values all-zero: p ~ 1e-160).
    // Same 256B for every warp -> L1 broadcast after first touch.
    const int probe = __ldg((const int*)idx + 2 * lane + 1);
    const bool is64 = (__ballot_sync(0xffffffffu, probe != 0) == 0u);

    const int i0 = warp_id * 2;
    const int i1 = i0 + 1;
    if (i0 >= n_rows) return;
    const bool has1 = (i1 < n_rows);

    // One idx load per lane per row (coalesced, read-once).
    int ja, jb = 0;
    if (is64) {
        ja = (int)__ldcs((const long long*)idx + (long long)i0 * 32 + lane);
        if (has1) jb = (int)__ldcs((const long long*)idx + (long long)i1 * 32 + lane);
    } else {
        ja = __ldcs((const int*)idx + i0 * 32 + lane);
        if (has1) jb = __ldcs((const int*)idx + i1 * 32 + lane);
    }

    const int wbase = lane >> 3;   // lane-group (0..3)
    const int seg   = lane & 7;    // float4 within the 32-float x row

    // Distribute needed neighbor indices via shuffle.
    int jwa[8], jwb[8];
#pragma unroll
    for (int it = 0; it < 8; it++) {
        jwa[it] = __shfl_sync(0xffffffffu, ja, it * 4 + wbase);
        jwb[it] = __shfl_sync(0xffffffffu, jb, it * 4 + wbase);
    }

    // 16 independent gathers (MLP=16). .cg: x can't live in L1 (12.8MB
    // random working set), skip L1 allocate.
    float4 va[8], vb[8];
#pragma unroll
    for (int it = 0; it < 8; it++)
        va[it] = __ldcg(x4 + (long long)jwa[it] * 8 + seg);
    if (has1) {
#pragma unroll
        for (int it = 0; it < 8; it++)
            vb[it] = __ldcg(x4 + (long long)jwb[it] * 8 + seg);
    }

    // Coalesced streaming stores (output never re-read).
    float4* __restrict__ orow0 = out4 + (long long)i0 * ROW_F4;
#pragma unroll
    for (int it = 0; it < 8; it++)
        __stcs(orow0 + it * 32 + lane, va[it]);
    if (has1) {
        float4* __restrict__ orow1 = out4 + (long long)i1 * ROW_F4;
#pragma unroll
        for (int it = 0; it < 8; it++)
            __stcs(orow1 + it * 32 + lane, vb[it]);

        // Packed tail: lanes 0-15 -> row0 [dis|angle], lanes 16-31 -> row1.
        float4 tv;
        if (lane < 8)        tv = __ldcs(dis4 + i0 * 8 + lane);
        else if (lane < 16)  tv = __ldcs(ang4 + i0 * 8 + (lane - 8));
        else if (lane < 24)  tv = __ldcs(dis4 + i1 * 8 + (lane - 16));
        else                 tv = __ldcs(ang4 + i1 * 8 + (lane - 24));

        if (lane < 16) __stcs(orow0 + 256 + lane, tv);
        else           __stcs(orow1 + 256 + (lane - 16), tv);
    } else {
        if (lane < 8)
            __stcs(orow0 + 256 + lane, __ldcs(dis4 + i0 * 8 + lane));
        else if (lane < 16)
            __stcs(orow0 + 256 + lane, __ldcs(ang4 + i0 * 8 + (lane - 8)));
    }
}

extern "C" void kernel_launch(void* const* d_in, const int* in_sizes, int n_in,
                              void* d_out, int out_size)
{
    const float4* x4   = (const float4*)d_in[0];
    const void*   idx  = d_in[1];
    const float4* dis4 = (const float4*)d_in[2];
    const float4* ang4 = (const float4*)d_in[3];
    float4* out4 = (float4*)d_out;

    const int n_rows = in_sizes[0] / 32;   // N

    const int threads = 256;                        // 8 warps/block
    const int rows_per_block = 16;                  // 2 rows per warp
    const int blocks = (n_rows + rows_per_block - 1) / rows_per_block;
    fused_gather_concat_warp2_kernel<<<blocks, threads>>>(x4, idx, dis4, ang4,
                                                          out4, n_rows);
}